// round 7
// baseline (speedup 1.0000x reference)
#include <cuda_runtime.h>
#include <cuda_fp16.h>
#include <cstdint>

// Problem shape (fixed): B=32, Q=512, K=512, D=1024
#define NB   32
#define NQ   512
#define NK   512
#define ND   1024

#define BM 128
#define BN 128
#define KC 32                  // K elements per chunk
#define NCHUNK (ND / KC)       // 32
#define THREADS 256
#define NSTAGE 3

// SMEM tile geometry: fp16 plane = 128 rows x 32 halfs (64B data) padded to 80B
#define ROWB    80
#define PLANE_B (128 * ROWB)          // 10240
#define STAGE_B (4 * PLANE_B)         // 40960  (Ahi | Alo | Bhi | Blo)
#define SMEM_BYTES (NSTAGE * STAGE_B) // 122880

#define NEG_INF (__int_as_float(0xff800000))

// fp16x2 scale by 2^-11 (exact exponent shift): half(2^-11) = 0x1000
#define H2_SCALE_DOWN 0x10001000u

// ---------------------------------------------------------------------------
// fp16 hi/lo scratch planes (device globals -- no allocation in kernel_launch)
// ---------------------------------------------------------------------------
#define ELEMS (NB * NQ * ND)   // 16777216 per tensor
__device__ __align__(16) __half g_Qh[ELEMS];
__device__ __align__(16) __half g_Ql[ELEMS];
__device__ __align__(16) __half g_Kh[ELEMS];
__device__ __align__(16) __half g_Kl[ELEMS];

// ---------------------------------------------------------------------------
// helpers
// ---------------------------------------------------------------------------
__device__ __forceinline__ uint32_t smem_u32(const void* p) {
    uint32_t a;
    asm("{ .reg .u64 t; cvta.to.shared.u64 t, %1; cvt.u32.u64 %0, t; }"
        : "=r"(a) : "l"(p));
    return a;
}

__device__ __forceinline__ uint32_t hmul2(uint32_t a, uint32_t s) {
    uint32_t r;
    asm("mul.f16x2 %0, %1, %2;" : "=r"(r) : "r"(a), "r"(s));
    return r;
}

#define CP_ASYNC16(dst, src) \
    asm volatile("cp.async.cg.shared.global [%0], [%1], 16;" :: "r"(dst), "l"(src))
#define CP_COMMIT() asm volatile("cp.async.commit_group;" ::: "memory")
#define CP_WAIT1()  asm volatile("cp.async.wait_group 1;" ::: "memory")

#define LDSM4(r0, r1, r2, r3, a)                                                \
    asm volatile("ldmatrix.sync.aligned.m8n8.x4.shared.b16 {%0,%1,%2,%3}, [%4];" \
                 : "=r"(r0), "=r"(r1), "=r"(r2), "=r"(r3) : "r"(a))

#define MMA161616(c, a0, a1, a2, a3, b0, b1)                                     \
    asm volatile(                                                                \
        "mma.sync.aligned.m16n8k16.row.col.f32.f16.f16.f32 "                     \
        "{%0,%1,%2,%3}, {%4,%5,%6,%7}, {%8,%9}, {%0,%1,%2,%3};"                  \
        : "+f"((c)[0]), "+f"((c)[1]), "+f"((c)[2]), "+f"((c)[3])                 \
        : "r"(a0), "r"(a1), "r"(a2), "r"(a3), "r"(b0), "r"(b1))

// ---------------------------------------------------------------------------
// Kernel 0: streaming fp32 -> (hi fp16, lo' fp16 = (x-hi)*2048) split.
// 8 elements per thread, fully coalesced.
// ---------------------------------------------------------------------------
__global__ __launch_bounds__(256)
void convert_kernel(const float* __restrict__ src,
                    __half* __restrict__ hi,
                    __half* __restrict__ lo)
{
    const size_t i = ((size_t)blockIdx.x * 256 + threadIdx.x) * 8;
    float4 a = *(const float4*)(src + i);
    float4 b = *(const float4*)(src + i + 4);

    __half2 h0 = __floats2half2_rn(a.x, a.y);
    __half2 h1 = __floats2half2_rn(a.z, a.w);
    __half2 h2 = __floats2half2_rn(b.x, b.y);
    __half2 h3 = __floats2half2_rn(b.z, b.w);

    __half2 l0 = __floats2half2_rn((a.x - __low2float(h0)) * 2048.0f,
                                   (a.y - __high2float(h0)) * 2048.0f);
    __half2 l1 = __floats2half2_rn((a.z - __low2float(h1)) * 2048.0f,
                                   (a.w - __high2float(h1)) * 2048.0f);
    __half2 l2 = __floats2half2_rn((b.x - __low2float(h2)) * 2048.0f,
                                   (b.y - __high2float(h2)) * 2048.0f);
    __half2 l3 = __floats2half2_rn((b.z - __low2float(h3)) * 2048.0f,
                                   (b.w - __high2float(h3)) * 2048.0f);

    *(uint4*)(hi + i) = make_uint4(*(uint32_t*)&h0, *(uint32_t*)&h1,
                                   *(uint32_t*)&h2, *(uint32_t*)&h3);
    *(uint4*)(lo + i) = make_uint4(*(uint32_t*)&l0, *(uint32_t*)&l1,
                                   *(uint32_t*)&l2, *(uint32_t*)&l3);
}

// ---------------------------------------------------------------------------
// Kernel 1: batched NT GEMM, fp32 emulated via 3x fp16 mma.sync, operands
// pre-split to fp16 hi/lo planes. 128x128 tile, KC=32 chunks, 3-stage
// cp.async pipeline, ldmatrix fragment loads, 8 warps x (64x32) warp tiles.
// ---------------------------------------------------------------------------
__global__ __launch_bounds__(THREADS, 1)
void gemm_hmma_kernel(float* __restrict__ C)
{
    extern __shared__ __align__(16) char smem[];
    const uint32_t sb = smem_u32(smem);

    const int tid  = threadIdx.x;
    const int wid  = tid >> 5;
    const int lane = tid & 31;
    const int gid  = lane >> 2;
    const int tig  = lane & 3;

    const int wm = wid & 1;           // 0..1 -> 64 rows
    const int wn = wid >> 1;          // 0..3 -> 32 cols

    const int b  = blockIdx.z;
    const int m0 = blockIdx.y * BM;
    const int n0 = blockIdx.x * BN;

    const size_t Aoff = (size_t)b * NQ * ND + (size_t)m0 * ND;
    const size_t Boff = (size_t)b * NK * ND + (size_t)n0 * ND;
    float* Cb = C + (size_t)b * NQ * NK;

    const __half* pb[4] = { g_Qh + Aoff, g_Ql + Aoff, g_Kh + Boff, g_Kl + Boff };

    // cp.async per-thread geometry: 8 issues/stage; t -> plane t>>1,
    // row = (t&1)*64 + tid>>2, col16 = tid&3
    const int rA = tid >> 2;
    const int c16 = tid & 3;

    // ldmatrix per-lane invariant addressing
    const int arow_lane = wm * 64 + (lane & 15);
    const uint32_t akh  = (uint32_t)((lane >> 4) * 16);
    const int brow_lane = wn * 32 + ((lane >> 4) * 8) + (lane & 7);
    const uint32_t bkh  = (uint32_t)(((lane >> 3) & 1) * 16);

    float acc[4][4][4];
#pragma unroll
    for (int i = 0; i < 4; i++)
#pragma unroll
        for (int j = 0; j < 4; j++)
#pragma unroll
            for (int k = 0; k < 4; k++) acc[i][j][k] = 0.0f;

    auto issue_stage = [&](int kc, int buf) {
        const uint32_t sdst = sb + buf * STAGE_B;
#pragma unroll
        for (int t = 0; t < 8; t++) {
            const int p   = t >> 1;
            const int row = (t & 1) * 64 + rA;
            const __half* src = pb[p] + (size_t)row * ND + kc * KC + c16 * 8;
            const uint32_t dst = sdst + p * PLANE_B + row * ROWB + c16 * 16;
            CP_ASYNC16(dst, src);
        }
    };

    // prologue: stages 0 and 1 in flight
    issue_stage(0, 0); CP_COMMIT();
    issue_stage(1, 1); CP_COMMIT();

    for (int kc = 0; kc < NCHUNK; kc++) {
        const int buf = kc % NSTAGE;
        CP_WAIT1();
        __syncthreads();

        // keep the pipeline full before computing
        if (kc + 2 < NCHUNK) issue_stage(kc + 2, (kc + 2) % NSTAGE);
        CP_COMMIT();

        const uint32_t st  = sb + buf * STAGE_B;
        const uint32_t stA = st;                     // Ahi
        const uint32_t stAl = st + PLANE_B;          // Alo
        const uint32_t stB = st + 2 * PLANE_B;       // Bhi
        const uint32_t stBl = st + 3 * PLANE_B;      // Blo

#pragma unroll
        for (int ks = 0; ks < 2; ks++) {
            const uint32_t kofs = ks * 32;

            uint32_t ah[4][4], bh[4][2];
#pragma unroll
            for (int mt = 0; mt < 4; mt++) {
                const uint32_t a = stA + (arow_lane + mt * 16) * ROWB + akh + kofs;
                LDSM4(ah[mt][0], ah[mt][1], ah[mt][2], ah[mt][3], a);
            }
#pragma unroll
            for (int ntp = 0; ntp < 2; ntp++) {
                const uint32_t a = stB + (brow_lane + ntp * 16) * ROWB + bkh + kofs;
                LDSM4(bh[2 * ntp][0], bh[2 * ntp][1],
                      bh[2 * ntp + 1][0], bh[2 * ntp + 1][1], a);
            }
            // pass 1: hi x hi
#pragma unroll
            for (int mt = 0; mt < 4; mt++)
#pragma unroll
                for (int nt = 0; nt < 4; nt++)
                    MMA161616(acc[mt][nt], ah[mt][0], ah[mt][1], ah[mt][2], ah[mt][3],
                              bh[nt][0], bh[nt][1]);

            // pass 2: (hi_a * 2^-11) x lo_b'
            uint32_t bl[4][2], as[4][4];
#pragma unroll
            for (int ntp = 0; ntp < 2; ntp++) {
                const uint32_t a = stBl + (brow_lane + ntp * 16) * ROWB + bkh + kofs;
                LDSM4(bl[2 * ntp][0], bl[2 * ntp][1],
                      bl[2 * ntp + 1][0], bl[2 * ntp + 1][1], a);
            }
#pragma unroll
            for (int mt = 0; mt < 4; mt++)
#pragma unroll
                for (int q = 0; q < 4; q++)
                    as[mt][q] = hmul2(ah[mt][q], H2_SCALE_DOWN);
#pragma unroll
            for (int mt = 0; mt < 4; mt++)
#pragma unroll
                for (int nt = 0; nt < 4; nt++)
                    MMA161616(acc[mt][nt], as[mt][0], as[mt][1], as[mt][2], as[mt][3],
                              bl[nt][0], bl[nt][1]);

            // pass 3: lo_a' x (hi_b * 2^-11)
            uint32_t al[4][4], bs[4][2];
#pragma unroll
            for (int mt = 0; mt < 4; mt++) {
                const uint32_t a = stAl + (arow_lane + mt * 16) * ROWB + akh + kofs;
                LDSM4(al[mt][0], al[mt][1], al[mt][2], al[mt][3], a);
            }
#pragma unroll
            for (int nt = 0; nt < 4; nt++) {
                bs[nt][0] = hmul2(bh[nt][0], H2_SCALE_DOWN);
                bs[nt][1] = hmul2(bh[nt][1], H2_SCALE_DOWN);
            }
#pragma unroll
            for (int mt = 0; mt < 4; mt++)
#pragma unroll
                for (int nt = 0; nt < 4; nt++)
                    MMA161616(acc[mt][nt], al[mt][0], al[mt][1], al[mt][2], al[mt][3],
                              bs[nt][0], bs[nt][1]);
        }
        __syncthreads();
    }

    // epilogue
#pragma unroll
    for (int mt = 0; mt < 4; mt++) {
        const int mrow = m0 + wm * 64 + mt * 16 + gid;
#pragma unroll
        for (int nt = 0; nt < 4; nt++) {
            const int col = n0 + wn * 32 + nt * 8 + tig * 2;
            float* cp0 = Cb + (size_t)mrow * NK + col;
            float* cp1 = Cb + (size_t)(mrow + 8) * NK + col;
            *(float2*)cp0 = make_float2(acc[mt][nt][0], acc[mt][nt][1]);
            *(float2*)cp1 = make_float2(acc[mt][nt][2], acc[mt][nt][3]);
        }
    }
}

// ---------------------------------------------------------------------------
// Kernel 2: fused key-mask + softmax + logsumexp->sigmoid confidence.
// One warp per (b,q) row; mask staged through SMEM; float4 row I/O.
// ---------------------------------------------------------------------------
__global__ __launch_bounds__(256)
void softmax_mask_kernel(float* __restrict__ attn,
                         float* __restrict__ conf,
                         const float* __restrict__ keys,
                         const float* __restrict__ tptr,
                         const float* __restrict__ bptr,
                         int writeConf)
{
    __shared__ __align__(16) float k0s[NK];

    const int lane = threadIdx.x & 31;
    const int w    = threadIdx.x >> 5;
    const int row0 = blockIdx.x * 8;
    const int b    = row0 >> 9;

    const float* kp = keys + (size_t)b * NK * ND;
    for (int k = threadIdx.x; k < NK; k += 256)
        k0s[k] = __ldg(kp + (size_t)k * ND);       // keys[b,k,0]
    __syncthreads();

    const int row = row0 + w;
    float4* rp4 = (float4*)(attn + (size_t)row * NK);
    const float4* m4p = (const float4*)k0s;

    float x[16];
#pragma unroll
    for (int i = 0; i < 4; i++) {
        float4 v = rp4[i * 32 + lane];
        float4 mk = m4p[i * 32 + lane];
        x[4 * i + 0] = (mk.x == 0.0f) ? NEG_INF : v.x;
        x[4 * i + 1] = (mk.y == 0.0f) ? NEG_INF : v.y;
        x[4 * i + 2] = (mk.z == 0.0f) ? NEG_INF : v.z;
        x[4 * i + 3] = (mk.w == 0.0f) ? NEG_INF : v.w;
    }

    float m = x[0];
#pragma unroll
    for (int i = 1; i < 16; i++) m = fmaxf(m, x[i]);
#pragma unroll
    for (int o = 16; o > 0; o >>= 1)
        m = fmaxf(m, __shfl_xor_sync(0xffffffffu, m, o));

    float e[16];
    float sum = 0.0f;
#pragma unroll
    for (int i = 0; i < 16; i++) {
        e[i] = __expf(x[i] - m);
        sum += e[i];
    }
#pragma unroll
    for (int o = 16; o > 0; o >>= 1)
        sum += __shfl_xor_sync(0xffffffffu, sum, o);

    const float inv = 1.0f / sum;
#pragma unroll
    for (int i = 0; i < 4; i++) {
        float4 o;
        o.x = e[4 * i + 0] * inv;
        o.y = e[4 * i + 1] * inv;
        o.z = e[4 * i + 2] * inv;
        o.w = e[4 * i + 3] * inv;
        rp4[i * 32 + lane] = o;
    }

    if (lane == 0 && writeConf) {
        const float lse  = m + __logf(sum);
        const float temp = *tptr;
        const float bia  = *bptr;
        const float z    = (lse + bia) * temp;
        conf[row] = 1.0f / (1.0f + __expf(-z));
    }
}

// ---------------------------------------------------------------------------
extern "C" void kernel_launch(void* const* d_in, const int* in_sizes, int n_in,
                              void* d_out, int out_size)
{
    const float* q  = (const float*)d_in[0];
    const float* k  = (const float*)d_in[1];
    const float* t  = (const float*)d_in[2];
    const float* bi = (const float*)d_in[3];

    float* attn = (float*)d_out;
    const long long attnElems = (long long)NB * NQ * NK;       // 8388608
    const int writeConf = (out_size >= attnElems + NB * NQ) ? 1 : 0;
    float* conf = attn + attnElems;

    static int smemSet = 0;
    if (!smemSet) {
        cudaFuncSetAttribute(gemm_hmma_kernel,
                             cudaFuncAttributeMaxDynamicSharedMemorySize, SMEM_BYTES);
        smemSet = 1;
    }

    // resolve device-global scratch addresses (no allocation)
    static __half *Qh = nullptr, *Ql = nullptr, *Kh = nullptr, *Kl = nullptr;
    if (!Qh) {
        cudaGetSymbolAddress((void**)&Qh, g_Qh);
        cudaGetSymbolAddress((void**)&Ql, g_Ql);
        cudaGetSymbolAddress((void**)&Kh, g_Kh);
        cudaGetSymbolAddress((void**)&Kl, g_Kl);
    }

    convert_kernel<<<ELEMS / (256 * 8), 256>>>(q, Qh, Ql);
    convert_kernel<<<ELEMS / (256 * 8), 256>>>(k, Kh, Kl);

    dim3 grid(NK / BN, NQ / BM, NB);        // (4, 4, 32)
    gemm_hmma_kernel<<<grid, THREADS, SMEM_BYTES>>>(attn);

    softmax_mask_kernel<<<(NB * NQ) / 8, 256>>>(attn, conf, k, t, bi, writeConf);
}